// round 13
// baseline (speedup 1.0000x reference)
#include <cuda_runtime.h>
#include <cstdint>

#define NB_B 8192
#define LOD 60
#define LSD 120
#define AD 10
#define NB 15
#define HH 60
#define BX 64
#define BY 12
#define NT 768

typedef unsigned long long u64;

// ---- device scratch ----
__device__ float4 g_tmb[LOD * 7 * NB];     // (t11,t21,t12,t22) banded, k fastest
__device__ float  g_coef[NB * NB_B];       // softmax coefs [k][b]
__device__ float  g_ctlT[NB_B * LSD];      // control, row-major [b][c]
__device__ float  g_tc[LSD];               // elup1(log_noise)

#define FMA2(acc, a, b) asm("fma.rn.f32x2 %0, %1, %2, %0;" : "+l"(acc) : "l"(a), "l"(b))
__device__ __forceinline__ float2 U2F(u64 v){ float2 r; asm("mov.b64 {%0,%1},%2;" : "=f"(r.x), "=f"(r.y) : "l"(v)); return r; }
__device__ __forceinline__ u64 F2U(float x, float y){ u64 r; asm("mov.b64 %0,{%1,%2};" : "=l"(r) : "f"(x), "f"(y)); return r; }
__device__ __forceinline__ u64 LDS64(uint32_t a){ u64 r; asm("ld.shared.b64 %0,[%1];" : "=l"(r) : "r"(a)); return r; }

// ======================= prep kernel (primary; full chip) =======================
// blocks 0..255: coef softmax + control MLP, 32 batch each, block (32,16)
// blocks 256..268: tmb pack (+ tc on 256)
#define PAD 33
#define PP_PM  0        // 120*33 = 3960 ; reused as ctl stage
#define PP_LG  3960     // 15*33 = 495
#define PP_ACT 4455     // 10*33 = 330
#define PP_H   4785     // 60*33 = 1980
#define PP_WC  6765     // 1800
#define PP_W1  8565     // 600
#define PP_W2  9165     // 7200
#define PP_B1  16365    // 60
#define PP_B2  16425    // 120
#define PP_BC  16545    // 15
#define PP_SMEM 16560

__global__ void __launch_bounds__(512, 2) prep_kernel(
    const float* __restrict__ post_mean, const float* __restrict__ action,
    const float* __restrict__ tm11, const float* __restrict__ tm12,
    const float* __restrict__ tm21, const float* __restrict__ tm22,
    const float* __restrict__ log_noise,
    const float* __restrict__ w_coef, const float* __restrict__ b_coef,
    const float* __restrict__ w_c1, const float* __restrict__ b_c1,
    const float* __restrict__ w_c2, const float* __restrict__ b_c2)
{
    const int bid = blockIdx.x;
    const int bl = threadIdx.x;          // 0..31
    const int yy = threadIdx.y;          // 0..15
    const int tid = yy * 32 + bl;

    if (bid >= 256) {                    // tmb pack + tc
        if (bid == 256 && tid < LSD) {
            float x = log_noise[tid];
            g_tc[tid] = (x < 0.f) ? expf(x) : x + 1.f;
        }
        int idx = (bid - 256) * 512 + tid;
        if (idx < LOD * 7 * NB) {
            int k = idx % NB;
            int jj = (idx / NB) % 7;
            int i = idx / (NB * 7);
            int j = i + jj - 3;
            float4 v = make_float4(0.f, 0.f, 0.f, 0.f);
            if (j >= 0 && j < LOD) {
                int off = k * LOD * LOD + i * LOD + j;
                v.x = tm11[off]; v.y = tm21[off];
                v.z = tm12[off]; v.w = tm22[off];
            }
            g_tmb[idx] = v;
        }
        return;
    }

    extern __shared__ float sp[];
    const int b0 = bid * 32;

    for (int e = tid; e < 32 * LSD; e += 512) {
        int b = e / LSD, d = e % LSD;
        sp[PP_PM + d * PAD + b] = post_mean[(b0 + b) * LSD + d];
    }
    for (int e = tid; e < 32 * AD; e += 512) {
        int b = e / AD, d = e % AD;
        sp[PP_ACT + d * PAD + b] = action[(b0 + b) * AD + d];
    }
    for (int e = tid; e < NB * LSD; e += 512) sp[PP_WC + e] = w_coef[e];
    for (int e = tid; e < HH * AD; e += 512)  sp[PP_W1 + e] = w_c1[e];
    for (int e = tid; e < LSD * HH; e += 512) sp[PP_W2 + e] = w_c2[e];
    if (tid < HH)  sp[PP_B1 + tid] = b_c1[tid];
    if (tid < LSD) sp[PP_B2 + tid] = b_c2[tid];
    if (tid < NB)  sp[PP_BC + tid] = b_coef[tid];
    __syncthreads();

    // logits (one k per y row)
    if (yy < NB) {
        float lg = sp[PP_BC + yy];
        #pragma unroll 4
        for (int d = 0; d < LSD; d++)
            lg = fmaf(sp[PP_WC + yy * LSD + d], sp[PP_PM + d * PAD + bl], lg);
        sp[PP_LG + yy * PAD + bl] = lg;
    }
    // hidden layer
    #pragma unroll
    for (int t = 0; t < 4; t++) {
        int i = yy + 16 * t;
        if (i < HH) {
            float hv = sp[PP_B1 + i];
            #pragma unroll
            for (int d = 0; d < AD; d++)
                hv = fmaf(sp[PP_W1 + i * AD + d], sp[PP_ACT + d * PAD + bl], hv);
            sp[PP_H + i * PAD + bl] = fmaxf(hv, 0.f);
        }
    }
    __syncthreads();

    // softmax per batch element (warp 0)
    if (yy == 0) {
        float mx = -1e30f;
        #pragma unroll
        for (int k = 0; k < NB; k++) mx = fmaxf(mx, sp[PP_LG + k * PAD + bl]);
        float ex[NB], sum = 0.f;
        #pragma unroll
        for (int k = 0; k < NB; k++) {
            ex[k] = __expf(sp[PP_LG + k * PAD + bl] - mx);
            sum += ex[k];
        }
        float inv = 1.f / sum;
        #pragma unroll
        for (int k = 0; k < NB; k++)
            g_coef[k * NB_B + b0 + bl] = ex[k] * inv;
    }
    // control output -> stage into PM region (dead now)
    #pragma unroll
    for (int t = 0; t < 8; t++) {
        int c = yy + 16 * t;
        if (c < LSD) {
            float ctl = sp[PP_B2 + c];
            #pragma unroll 4
            for (int m = 0; m < HH; m++)
                ctl = fmaf(sp[PP_W2 + c * HH + m], sp[PP_H + m * PAD + bl], ctl);
            sp[PP_PM + c * PAD + bl] = ctl;
        }
    }
    __syncthreads();

    // coalesced transposed store of control
    for (int e = tid; e < 32 * LSD; e += 512) {
        int b = e / LSD, c = e % LSD;
        g_ctlT[(b0 + b) * LSD + c] = sp[PP_PM + c * PAD + b];
    }
}

// ======================= main kernel (secondary; R4 hot path) =======================
// smem float offsets
#define SM_TMB   0        // 25200 floats; reused as stage[300*67]
#define SM_MUML  25200    // float2[60][66] -> 7920
#define SM_CUCL  33120    // 7920
#define SM_CS2   41040    // 3960
#define SM_COEF  45000    // u64[15][64] -> 1920
#define SM_TC    46920    // 120
#define SM_FLOATS 47040   // 188160 bytes

template<int J0, int JN>
__device__ __forceinline__ void mix_pass(
    uint32_t tmbRow, uint32_t coefA, u64* aX, u64* aY)
{
    #pragma unroll
    for (int jj = 0; jj < JN; jj++) { aX[jj] = 0; aY[jj] = 0; }
    #pragma unroll
    for (int k = 0; k < NB; k++) {
        u64 c2 = LDS64(coefA + (uint32_t)(k * 512));
        #pragma unroll
        for (int jj = 0; jj < JN; jj++) {
            u64 vX, vY;   // (t11,t21), (t12,t22) — warp-uniform broadcast
            asm("ld.shared.v2.u64 {%0,%1},[%2];"
                : "=l"(vX), "=l"(vY)
                : "r"(tmbRow + (uint32_t)(((J0 + jj) * NB + k) * 16)));
            FMA2(aX[jj], c2, vX);
            FMA2(aY[jj], c2, vY);
        }
    }
}

__device__ __forceinline__ void combine(
    u64 aXv, u64 aYv, bool diag, int jc, int x, const float* __restrict__ sm,
    float& nmu, float& nml, float& ncu, float& ncl, float& ncs)
{
    float2 X = U2F(aXv), Y = U2F(aYv);
    float t11 = X.x, t21 = X.y, t12 = Y.x, t22 = Y.y;
    if (diag) { t11 += 1.f; t22 += 1.f; }
    float2 mm = ((const float2*)(sm + SM_MUML))[jc * 66 + x];   // (mu, ml)
    float2 cc = ((const float2*)(sm + SM_CUCL))[jc * 66 + x];   // (cu, cl)
    float cs2 = sm[SM_CS2 + jc * 66 + x];
    nmu = fmaf(t11, mm.x, fmaf(t12, mm.y, nmu));
    nml = fmaf(t21, mm.x, fmaf(t22, mm.y, nml));
    ncu = fmaf(t11 * t11, cc.x, fmaf(t11 * t12, cs2, fmaf(t12 * t12, cc.y, ncu)));
    ncl = fmaf(t21 * t21, cc.x, fmaf(t21 * t22, cs2, fmaf(t22 * t22, cc.y, ncl)));
    ncs = fmaf(t21 * t11, cc.x,
          fmaf(0.5f * fmaf(t22, t11, t21 * t12), cs2,
          fmaf(t22 * t12, cc.y, ncs)));
}

__global__ void __launch_bounds__(NT, 1) acpredict_kernel(
    const float* __restrict__ post_mean, const float* __restrict__ cu_g,
    const float* __restrict__ cl_g, const float* __restrict__ cs_g,
    float* __restrict__ out)
{
    extern __shared__ float sm[];
    const int x   = threadIdx.x;           // 0..63 : batch element
    const int y   = threadIdx.y;           // 0..11 : row group
    const int tid = y * BX + x;
    const int b0  = blockIdx.x * BX;

    // ---- pre-sync loads: harness inputs only (overlap the prep kernel) ----
    for (int e = tid; e < BX * LSD; e += NT) {
        int bl = e / LSD, d = e % LSD;
        float v = post_mean[(b0 + bl) * LSD + d];
        int j = (d < LOD) ? d : d - LOD;
        sm[SM_MUML + (j * 66 + bl) * 2 + (d < LOD ? 0 : 1)] = v;
    }
    for (int e = tid; e < BX * LOD; e += NT) {
        int bl = e / LOD, j = e % LOD;
        sm[SM_CUCL + (j * 66 + bl) * 2 + 0] = cu_g[(b0 + bl) * LOD + j];
        sm[SM_CUCL + (j * 66 + bl) * 2 + 1] = cl_g[(b0 + bl) * LOD + j];
        sm[SM_CS2 + j * 66 + bl] = 2.f * cs_g[(b0 + bl) * LOD + j];
    }

    // ---- wait for prep kernel, then load its products ----
    cudaGridDependencySynchronize();
    {
        float4* t4 = (float4*)sm;
        for (int e = tid; e < LOD * 7 * NB; e += NT) t4[e] = g_tmb[e];
    }
    for (int e = tid; e < NB * BX; e += NT) {
        int k = e / BX, bl = e % BX;
        float c = g_coef[k * NB_B + b0 + bl];
        ((u64*)(sm + SM_COEF))[k * BX + bl] = F2U(c, c);
    }
    if (tid < LSD) sm[SM_TC + tid] = g_tc[tid];
    __syncthreads();

    // ---- mix + combine (R4 hot loop, unchanged) ----
    const uint32_t sbase = (uint32_t)__cvta_generic_to_shared(sm);
    const uint32_t coefA = sbase + SM_COEF * 4 + (uint32_t)x * 8u;

    float res[5][5];

    #pragma unroll
    for (int t = 0; t < 5; t++) {
        const int i = y + BY * t;
        const uint32_t tmbRow = sbase + (uint32_t)(i * 7 * NB * 16);
        float nmu = 0.f, nml = 0.f, ncu = 0.f, ncl = 0.f, ncs = 0.f;
        {   // jj 0..3
            u64 aX[4], aY[4];
            mix_pass<0, 4>(tmbRow, coefA, aX, aY);
            #pragma unroll
            for (int jj = 0; jj < 4; jj++) {
                int jc = max(i + jj - 3, 0);
                combine(aX[jj], aY[jj], jj == 3, jc, x, sm, nmu, nml, ncu, ncl, ncs);
            }
        }
        {   // jj 4..6
            u64 aX[3], aY[3];
            mix_pass<4, 3>(tmbRow, coefA, aX, aY);
            #pragma unroll
            for (int jj = 0; jj < 3; jj++) {
                int jc = min(i + 1 + jj, LOD - 1);
                combine(aX[jj], aY[jj], false, jc, x, sm, nmu, nml, ncu, ncl, ncs);
            }
        }
        res[t][0] = nmu; res[t][1] = nml;
        res[t][2] = ncu; res[t][3] = ncl; res[t][4] = ncs;
    }

    __syncthreads();                 // all tmb/input reads complete
    #pragma unroll
    for (int t = 0; t < 5; t++) {    // stage into dead tmb region, stride 67
        int i = y + BY * t;
        sm[(i)        * 67 + x] = res[t][0];
        sm[(LOD + i)  * 67 + x] = res[t][1];
        sm[(120 + i)  * 67 + x] = res[t][2];
        sm[(180 + i)  * 67 + x] = res[t][3];
        sm[(240 + i)  * 67 + x] = res[t][4];
    }
    __syncthreads();

    // ---- coalesced stores; fold in control (from global) + trans_cov ----
    for (int e = tid; e < BX * 300; e += NT) {
        int bl = e / 300, c = e % 300;
        float v = sm[c * 67 + bl];
        int bb = b0 + bl;
        if (c < 120) {
            v += __ldg(&g_ctlT[bb * LSD + c]);
            out[bb * 120 + c] = v;
        } else {
            if (c < 240) v += sm[SM_TC + (c - 120)];
            int blk = c / 60;        // 2, 3, 4
            out[NB_B * 60 * blk + bb * 60 + (c - blk * 60)] = v;
        }
    }
}

extern "C" void kernel_launch(void* const* d_in, const int* in_sizes, int n_in,
                              void* d_out, int out_size) {
    const float* post_mean = (const float*)d_in[0];
    const float* cu        = (const float*)d_in[1];
    const float* cl        = (const float*)d_in[2];
    const float* cs        = (const float*)d_in[3];
    const float* action    = (const float*)d_in[4];
    const float* tm11      = (const float*)d_in[5];
    const float* tm12      = (const float*)d_in[6];
    const float* tm21      = (const float*)d_in[7];
    const float* tm22      = (const float*)d_in[8];
    const float* log_noise = (const float*)d_in[9];
    const float* w_coef    = (const float*)d_in[10];
    const float* b_coef    = (const float*)d_in[11];
    const float* w_c1      = (const float*)d_in[12];
    const float* b_c1      = (const float*)d_in[13];
    const float* w_c2      = (const float*)d_in[14];
    const float* b_c2      = (const float*)d_in[15];
    float* out = (float*)d_out;

    static bool attr_done = false;
    if (!attr_done) {
        cudaFuncSetAttribute(prep_kernel,
            cudaFuncAttributeMaxDynamicSharedMemorySize, PP_SMEM * 4);
        cudaFuncSetAttribute(acpredict_kernel,
            cudaFuncAttributeMaxDynamicSharedMemorySize, SM_FLOATS * 4);
        attr_done = true;
    }

    // primary: full prep (coef softmax, control MLP, tmb pack, tc)
    dim3 pblk(32, 16);
    prep_kernel<<<256 + 13, pblk, PP_SMEM * 4>>>(
        post_mean, action, tm11, tm12, tm21, tm22, log_noise,
        w_coef, b_coef, w_c1, b_c1, w_c2, b_c2);

    // secondary: R4 main with PDL — input loads overlap prep
    cudaLaunchConfig_t cfg = {};
    cfg.gridDim = dim3(NB_B / BX);
    cfg.blockDim = dim3(BX, BY);
    cfg.dynamicSmemBytes = SM_FLOATS * 4;
    cfg.stream = 0;
    cudaLaunchAttribute at[1];
    at[0].id = cudaLaunchAttributeProgrammaticStreamSerialization;
    at[0].val.programmaticStreamSerializationAllowed = 1;
    cfg.attrs = at;
    cfg.numAttrs = 1;
    cudaLaunchKernelEx(&cfg, acpredict_kernel,
                       post_mean, cu, cl, cs, out);
}

// round 14
// speedup vs baseline: 1.1714x; 1.1714x over previous
#include <cuda_runtime.h>
#include <cstdint>

#define NB_B 8192
#define LOD 60
#define LSD 120
#define AD 10
#define NB 15
#define HH 60
#define BT 64      // batch tile per CTA
#define XT 32      // lane owns batches x and x+32
#define BY 20
#define NT 640

typedef unsigned long long u64;

// ---- device scratch ----
__device__ float4 g_tmb[LOD * 7 * NB];     // (t11,t21,t12,t22) banded, k fastest

#define FMA2(acc, a, b) asm("fma.rn.f32x2 %0, %1, %2, %0;" : "+l"(acc) : "l"(a), "l"(b))
__device__ __forceinline__ u64 MUL2(u64 a, u64 b){ u64 d; asm("mul.rn.f32x2 %0,%1,%2;" : "=l"(d) : "l"(a), "l"(b)); return d; }
__device__ __forceinline__ u64 ADD2(u64 a, u64 b){ u64 d; asm("add.rn.f32x2 %0,%1,%2;" : "=l"(d) : "l"(a), "l"(b)); return d; }
__device__ __forceinline__ float2 U2F(u64 v){ float2 r; asm("mov.b64 {%0,%1},%2;" : "=f"(r.x), "=f"(r.y) : "l"(v)); return r; }
__device__ __forceinline__ u64 F2U(float x, float y){ u64 r; asm("mov.b64 %0,{%1,%2};" : "=l"(r) : "f"(x), "f"(y)); return r; }
__device__ __forceinline__ u64 LDS64(uint32_t a){ u64 r; asm("ld.shared.b64 %0,[%1];" : "=l"(r) : "r"(a)); return r; }

// ======================= pack kernel (tiny, overlapped via PDL) =======================
__global__ void __launch_bounds__(512) pack_kernel(
    const float* __restrict__ tm11, const float* __restrict__ tm12,
    const float* __restrict__ tm21, const float* __restrict__ tm22)
{
    int idx = blockIdx.x * 512 + threadIdx.x;
    if (idx >= LOD * 7 * NB) return;
    int k = idx % NB;
    int jj = (idx / NB) % 7;
    int i = idx / (NB * 7);
    int j = i + jj - 3;
    float4 v = make_float4(0.f, 0.f, 0.f, 0.f);
    if (j >= 0 && j < LOD) {
        int off = k * LOD * LOD + i * LOD + j;
        v.x = tm11[off]; v.y = tm21[off];
        v.z = tm12[off]; v.w = tm22[off];
    }
    g_tmb[idx] = v;
}

// ======================= fused main kernel =======================
// persistent smem regions (float offsets). Input arrays hold batch-pair u64s:
// element (j, lane x) = (val for batch x, val for batch x+32)
#define SM_TMB   0        // 25200 floats; prep scratch first, then tmb (stage reuses rows)
#define SM_MU2   25200    // u64[60][33] -> 3960 floats
#define SM_ML2   29160    // 3960
#define SM_CU2   33120    // 3960
#define SM_CL2   37080    // 3960
#define SM_CS22  41040    // 3960 (pairs of 2*cs)
#define SM_COEF  45000    // u64[15][64] -> 1920
#define SM_TC    46920    // 120
#define SM_CTL   47040    // u64[120][33] adjacent-batch pairs -> 7920
#define SM_FLOATS 54960   // 219840 bytes
#define RB 15840          // region stride in bytes (3960 floats)

// prep scratch inside tmb region (dead before tmb load)
#define PW_WC   0         // dup pairs u64[15][120] -> 3600 floats
#define PW_W1   3600      // 600
#define PW_W2   4200      // dup pairs float2[120][60] -> 14400
#define PW_B1   18600     // 60
#define PW_B2   18660     // 120
#define PW_BC   18780     // 15 (+pad) -> 18800
#define PW_ACT  18800     // 10*66 = 660
#define PW_H    19460     // 60*66 = 3960
#define PW_LG   23420     // u64[15][33] -> 990 -> ends 24410 < 25200

// one k-walk over JN diagonals: ONE tmb load feeds both batch halves (4 chains)
template<int J0, int JN>
__device__ __forceinline__ void mix_halves(
    uint32_t tmbRow, uint32_t coefA,
    u64* aXA, u64* aYA, u64* aXB, u64* aYB)
{
    #pragma unroll
    for (int jj = 0; jj < JN; jj++) { aXA[jj]=0; aYA[jj]=0; aXB[jj]=0; aYB[jj]=0; }
    #pragma unroll
    for (int k = 0; k < NB; k++) {
        u64 cA = LDS64(coefA + (uint32_t)(k * 512));          // batch x
        u64 cB = LDS64(coefA + (uint32_t)(k * 512 + 256));    // batch x+32
        #pragma unroll
        for (int jj = 0; jj < JN; jj++) {
            u64 vX, vY;   // (t11,t21), (t12,t22) — warp-uniform broadcast, loaded ONCE
            asm("ld.shared.v2.u64 {%0,%1},[%2];"
                : "=l"(vX), "=l"(vY)
                : "r"(tmbRow + (uint32_t)(((J0 + jj) * NB + k) * 16)));
            FMA2(aXA[jj], cA, vX); FMA2(aYA[jj], cA, vY);
            FMA2(aXB[jj], cB, vX); FMA2(aYB[jj], cB, vY);
        }
    }
}

// batch-paired combine: all algebra in f32x2 over (batch x, batch x+32)
__device__ __forceinline__ void combine2(
    u64 aXA, u64 aYA, u64 aXB, u64 aYB, bool diag, uint32_t inA,
    u64& NMU, u64& NML, u64& NCU, u64& NCL, u64& NCS)
{
    const u64 ONE2  = 0x3f8000003f800000ULL;
    const u64 HALF2 = 0x3f0000003f000000ULL;
    float2 XA = U2F(aXA), YA = U2F(aYA), XB = U2F(aXB), YB = U2F(aYB);
    u64 T11 = F2U(XA.x, XB.x), T21 = F2U(XA.y, XB.y);
    u64 T12 = F2U(YA.x, YB.x), T22 = F2U(YA.y, YB.y);
    if (diag) { T11 = ADD2(T11, ONE2); T22 = ADD2(T22, ONE2); }
    u64 MU  = LDS64(inA);
    u64 ML  = LDS64(inA + RB);
    u64 CU  = LDS64(inA + 2 * RB);
    u64 CL  = LDS64(inA + 3 * RB);
    u64 CS2 = LDS64(inA + 4 * RB);
    FMA2(NMU, T11, MU); FMA2(NMU, T12, ML);
    FMA2(NML, T21, MU); FMA2(NML, T22, ML);
    u64 q;
    q = MUL2(T11, T11); FMA2(NCU, q, CU);
    q = MUL2(T11, T12); FMA2(NCU, q, CS2);
    q = MUL2(T12, T12); FMA2(NCU, q, CL);
    q = MUL2(T21, T21); FMA2(NCL, q, CU);
    q = MUL2(T21, T22); FMA2(NCL, q, CS2);
    q = MUL2(T22, T22); FMA2(NCL, q, CL);
    q = MUL2(T21, T11); FMA2(NCS, q, CU);
    u64 q2 = MUL2(T22, T11);
    u64 q3 = MUL2(T21, T12);
    q2 = ADD2(q2, q3);
    u64 csh = MUL2(CS2, HALF2);
    FMA2(NCS, q2, csh);
    q = MUL2(T22, T12); FMA2(NCS, q, CL);
}

__global__ void __launch_bounds__(NT, 1) acpredict_kernel(
    const float* __restrict__ post_mean, const float* __restrict__ cu_g,
    const float* __restrict__ cl_g, const float* __restrict__ cs_g,
    const float* __restrict__ action, const float* __restrict__ log_noise,
    const float* __restrict__ w_coef, const float* __restrict__ b_coef,
    const float* __restrict__ w_c1, const float* __restrict__ b_c1,
    const float* __restrict__ w_c2, const float* __restrict__ b_c2,
    float* __restrict__ out)
{
    extern __shared__ float sm[];
    const int x   = threadIdx.x;           // 0..31 : batch elements x and x+32
    const int y   = threadIdx.y;           // 0..19 : row group (ONE warp)
    const int tid = y * XT + x;
    const int b0  = blockIdx.x * BT;

    // ---- phase 0: load inputs + prep weights (tmb region holds scratch) ----
    for (int e = tid; e < BT * LSD; e += NT) {
        int bl = e / LSD, d = e % LSD;
        float v = post_mean[(b0 + bl) * LSD + d];
        int j = (d < LOD) ? d : d - LOD;
        int idx = (j * 33 + (bl & 31)) * 2 + (bl >> 5);
        sm[(d < LOD ? SM_MU2 : SM_ML2) + idx] = v;
    }
    for (int e = tid; e < BT * LOD; e += NT) {
        int bl = e / LOD, j = e % LOD;
        int idx = (j * 33 + (bl & 31)) * 2 + (bl >> 5);
        sm[SM_CU2 + idx]  = cu_g[(b0 + bl) * LOD + j];
        sm[SM_CL2 + idx]  = cl_g[(b0 + bl) * LOD + j];
        sm[SM_CS22 + idx] = 2.f * cs_g[(b0 + bl) * LOD + j];
    }
    for (int e = tid; e < BT * AD; e += NT) {
        int bl = e / AD, d = e % AD;
        sm[PW_ACT + d * 66 + bl] = action[(b0 + bl) * AD + d];
    }
    // w_coef duplicated pairs: u64[k][120] — cols 0..59 mu weights, 60..119 ml weights
    for (int e = tid; e < NB * LSD; e += NT) {
        int k = e / LSD, d = e % LSD;
        int j = (d < LOD) ? d : d - LOD;
        int col = (d < LOD) ? j : 60 + j;
        float v = w_coef[e];
        ((u64*)(sm + PW_WC))[k * 120 + col] = F2U(v, v);
    }
    for (int e = tid; e < HH * AD; e += NT)  sm[PW_W1 + e] = w_c1[e];
    for (int e = tid; e < LSD * HH; e += NT) {
        float v = w_c2[e];
        ((u64*)(sm + PW_W2))[e] = F2U(v, v);
    }
    if (tid < HH)  sm[PW_B1 + tid] = b_c1[tid];
    if (tid < LSD) sm[PW_B2 + tid] = b_c2[tid];
    if (tid < NB)  sm[PW_BC + tid] = b_coef[tid];
    if (tid < LSD) {
        float v = log_noise[tid];
        sm[SM_TC + tid] = (v < 0.f) ? __expf(v) : v + 1.f;
    }
    __syncthreads();

    // ---- phase 1: logits (batch-pair f32x2) + hidden layer ----
    for (int e = tid; e < NB * 32; e += NT) {          // 480 pair-items
        int k = e / 32, x2 = e % 32;
        u64 acc = 0;
        const u64* wcP = (const u64*)(sm + PW_WC) + k * 120;   // warp-uniform
        const u64* muP = (const u64*)(sm + SM_MU2);
        const u64* mlP = (const u64*)(sm + SM_ML2);
        #pragma unroll 4
        for (int j = 0; j < LOD; j++) {
            FMA2(acc, wcP[j],      muP[j * 33 + x2]);
            FMA2(acc, wcP[60 + j], mlP[j * 33 + x2]);
        }
        float bc = sm[PW_BC + k];
        ((u64*)(sm + PW_LG))[k * 33 + x2] = ADD2(acc, F2U(bc, bc));
    }
    for (int e = tid; e < HH * BT; e += NT) {
        int i = e / BT, bl = e % BT;
        float hv = sm[PW_B1 + i];
        #pragma unroll
        for (int d = 0; d < AD; d++)
            hv = fmaf(sm[PW_W1 + i * AD + d], sm[PW_ACT + d * 66 + bl], hv);
        sm[PW_H + i * 66 + bl] = fmaxf(hv, 0.f);
    }
    __syncthreads();

    // ---- phase 2: softmax (-> SM_COEF) + control MLP (channel-tiled x4) ----
    if (tid < BT) {
        const int bl = tid;
        const int lgOff = PW_LG + (bl & 31) * 2 + (bl >> 5);   // per-batch view of LG pairs
        float mx = -1e30f;
        #pragma unroll
        for (int k = 0; k < NB; k++) mx = fmaxf(mx, sm[lgOff + k * 66]);
        float ex[NB], sum = 0.f;
        #pragma unroll
        for (int k = 0; k < NB; k++) {
            ex[k] = __expf(sm[lgOff + k * 66] - mx);
            sum += ex[k];
        }
        float inv = 1.f / sum;
        #pragma unroll
        for (int k = 0; k < NB; k++) {
            float c = ex[k] * inv;
            ((u64*)(sm + SM_COEF))[k * BT + bl] = F2U(c, c);
        }
    }
    for (int e = tid; e < 30 * (BT / 2); e += NT) {
        int g = e / (BT / 2), blp = e % (BT / 2);
        int c0 = g * 4;
        u64 acc[4];
        #pragma unroll
        for (int q = 0; q < 4; q++) {
            float bb = sm[PW_B2 + c0 + q];
            acc[q] = F2U(bb, bb);
        }
        const u64* w2P = (const u64*)(sm + PW_W2);
        const u64* hP  = (const u64*)(sm + PW_H);
        #pragma unroll 4
        for (int m = 0; m < HH; m++) {
            u64 hm = hP[m * 33 + blp];
            #pragma unroll
            for (int q = 0; q < 4; q++)
                FMA2(acc[q], w2P[(c0 + q) * HH + m], hm);
        }
        #pragma unroll
        for (int q = 0; q < 4; q++)
            ((u64*)(sm + SM_CTL))[(c0 + q) * 33 + blp] = acc[q];
    }
    __syncthreads();

    // ---- phase 3: wait for pack kernel, load tmb into smem ----
    cudaGridDependencySynchronize();
    {
        float4* t4 = (float4*)sm;
        for (int e = tid; e < LOD * 7 * NB; e += NT) t4[e] = g_tmb[e];
    }
    __syncthreads();

    // ---- phase 4: one warp per row, batch-paired f32x2 combine ----
    const uint32_t sbase = (uint32_t)__cvta_generic_to_shared(sm);
    const uint32_t coefA = sbase + SM_COEF * 4 + (uint32_t)x * 8u;
    const uint32_t inBase = sbase + SM_MU2 * 4 + (uint32_t)x * 8u;

    #pragma unroll
    for (int t = 0; t < 3; t++) {
        const int i = y + BY * t;          // 0..59, each row owned by ONE warp
        const uint32_t tmbRow = sbase + (uint32_t)(i * 7 * NB * 16);

        u64 NMU = 0, NML = 0, NCU = 0, NCL = 0, NCS = 0;

        {   // pass A: jj 0..3
            u64 aXA[4], aYA[4], aXB[4], aYB[4];
            mix_halves<0, 4>(tmbRow, coefA, aXA, aYA, aXB, aYB);
            #pragma unroll
            for (int jj = 0; jj < 4; jj++) {
                int jc = max(i + jj - 3, 0);
                combine2(aXA[jj], aYA[jj], aXB[jj], aYB[jj], jj == 3,
                         inBase + (uint32_t)(jc * 264), NMU, NML, NCU, NCL, NCS);
            }
        }
        {   // pass B: jj 4..6
            u64 aXA[3], aYA[3], aXB[3], aYB[3];
            mix_halves<4, 3>(tmbRow, coefA, aXA, aYA, aXB, aYB);
            #pragma unroll
            for (int q = 0; q < 3; q++) {
                int jc = min(i + 1 + q, LOD - 1);
                combine2(aXA[q], aYA[q], aXB[q], aYB[q], false,
                         inBase + (uint32_t)(jc * 264), NMU, NML, NCU, NCL, NCS);
            }
        }

        // stage into this row's own dead tmb slot (u64 pair layout [q][32])
        // row i is owned solely by this warp — no cross-warp sync needed.
        u64* stg = (u64*)(sm + i * 420);
        stg[0 * 32 + x] = NMU;
        stg[1 * 32 + x] = NML;
        stg[2 * 32 + x] = NCU;
        stg[3 * 32 + x] = NCL;
        stg[4 * 32 + x] = NCS;
    }
    __syncthreads();

    // ---- phase 5: coalesced stores; fold in control + trans_cov ----
    // stage layout: value(q, row i, batch bl) at sm[i*420 + q*64 + 2*(bl&31) + (bl>>5)]
    for (int e = tid; e < BT * 300; e += NT) {
        int bl = e / 300, c = e % 300;
        int q = c / 60, i = c % 60;
        float v = sm[i * 420 + q * 64 + 2 * (bl & 31) + (bl >> 5)];
        int bb = b0 + bl;
        if (c < 120) {
            v += sm[SM_CTL + c * 66 + bl];
            out[bb * 120 + c] = v;
        } else {
            if (c < 240) v += sm[SM_TC + (c - 120)];
            out[NB_B * 60 * q + bb * 60 + i] = v;
        }
    }
}

extern "C" void kernel_launch(void* const* d_in, const int* in_sizes, int n_in,
                              void* d_out, int out_size) {
    const float* post_mean = (const float*)d_in[0];
    const float* cu        = (const float*)d_in[1];
    const float* cl        = (const float*)d_in[2];
    const float* cs        = (const float*)d_in[3];
    const float* action    = (const float*)d_in[4];
    const float* tm11      = (const float*)d_in[5];
    const float* tm12      = (const float*)d_in[6];
    const float* tm21      = (const float*)d_in[7];
    const float* tm22      = (const float*)d_in[8];
    const float* log_noise = (const float*)d_in[9];
    const float* w_coef    = (const float*)d_in[10];
    const float* b_coef    = (const float*)d_in[11];
    const float* w_c1      = (const float*)d_in[12];
    const float* b_c1      = (const float*)d_in[13];
    const float* w_c2      = (const float*)d_in[14];
    const float* b_c2      = (const float*)d_in[15];
    float* out = (float*)d_out;

    static bool attr_done = false;
    if (!attr_done) {
        cudaFuncSetAttribute(acpredict_kernel,
            cudaFuncAttributeMaxDynamicSharedMemorySize, SM_FLOATS * 4);
        attr_done = true;
    }

    // primary: tiny tmb pack
    pack_kernel<<<13, 512>>>(tm11, tm12, tm21, tm22);

    // secondary: fused main kernel with PDL (preamble overlaps pack)
    cudaLaunchConfig_t cfg = {};
    cfg.gridDim = dim3(NB_B / BT);
    cfg.blockDim = dim3(XT, BY);
    cfg.dynamicSmemBytes = SM_FLOATS * 4;
    cfg.stream = 0;
    cudaLaunchAttribute at[1];
    at[0].id = cudaLaunchAttributeProgrammaticStreamSerialization;
    at[0].val.programmaticStreamSerializationAllowed = 1;
    cfg.attrs = at;
    cfg.numAttrs = 1;
    cudaLaunchKernelEx(&cfg, acpredict_kernel,
                       post_mean, cu, cl, cs, action, log_noise,
                       w_coef, b_coef, w_c1, b_c1, w_c2, b_c2, out);
}

// round 15
// speedup vs baseline: 1.1722x; 1.0007x over previous
#include <cuda_runtime.h>
#include <cstdint>

#define NB_B 8192
#define LOD 60
#define LSD 120
#define AD 10
#define NB 15
#define HH 60
#define BX 64
#define BY 10
#define NT 640
#define RPT 6      // rows per thread: 60 = BY * RPT

typedef unsigned long long u64;

// ---- device scratch ----
__device__ float4 g_tmb[LOD * 7 * NB];     // (t11,t21,t12,t22) banded, k fastest

#define FMA2(acc, a, b) asm("fma.rn.f32x2 %0, %1, %2, %0;" : "+l"(acc) : "l"(a), "l"(b))
__device__ __forceinline__ float2 U2F(u64 v){ float2 r; asm("mov.b64 {%0,%1},%2;" : "=f"(r.x), "=f"(r.y) : "l"(v)); return r; }
__device__ __forceinline__ u64 F2U(float x, float y){ u64 r; asm("mov.b64 %0,{%1,%2};" : "=l"(r) : "f"(x), "f"(y)); return r; }
__device__ __forceinline__ u64 LDS64(uint32_t a){ u64 r; asm("ld.shared.b64 %0,[%1];" : "=l"(r) : "r"(a)); return r; }

// ======================= pack kernel (tiny, overlapped via PDL) =======================
__global__ void __launch_bounds__(512) pack_kernel(
    const float* __restrict__ tm11, const float* __restrict__ tm12,
    const float* __restrict__ tm21, const float* __restrict__ tm22)
{
    int idx = blockIdx.x * 512 + threadIdx.x;
    if (idx >= LOD * 7 * NB) return;
    int k = idx % NB;
    int jj = (idx / NB) % 7;
    int i = idx / (NB * 7);
    int j = i + jj - 3;
    float4 v = make_float4(0.f, 0.f, 0.f, 0.f);
    if (j >= 0 && j < LOD) {
        int off = k * LOD * LOD + i * LOD + j;
        v.x = tm11[off]; v.y = tm21[off];
        v.z = tm12[off]; v.w = tm22[off];
    }
    g_tmb[idx] = v;
}

// ======================= fused main kernel =======================
// persistent smem regions (float offsets)
#define SM_TMB   0        // 25200 floats; prep scratch first, then tmb (stage reuses tmb rows)
#define SM_MUML  25200    // float2[60][66] -> 7920
#define SM_CUCL  33120    // 7920
#define SM_CS2   41040    // 3960
#define SM_COEF  45000    // u64[15][64] -> 1920
#define SM_TC    46920    // 120
#define SM_CTL   47040    // float2 pairs -> 7920
#define SM_FLOATS 54960   // 219840 bytes

// prep scratch inside tmb region (dead before tmb load)
#define PW_WC   0         // packed float2[15][60] -> 1800
#define PW_W1   1800      // 600
#define PW_W2   2400      // duplicated float2[120][60] -> 14400
#define PW_B1   16800     // 60
#define PW_B2   16860     // 120
#define PW_BC   16980     // 15 (+pad)
#define PW_ACT  17000     // 10*66 = 660
#define PW_H    17660     // 60*66 = 3960
#define PW_LG   21620     // 15*66 = 990 -> 22610 < 25200

__device__ __forceinline__ void combine(
    u64 aXv, u64 aYv, bool diag, int jc, int x, const float* __restrict__ sm,
    float& nmu, float& nml, float& ncu, float& ncl, float& ncs)
{
    float2 X = U2F(aXv), Y = U2F(aYv);
    float t11 = X.x, t21 = X.y, t12 = Y.x, t22 = Y.y;
    if (diag) { t11 += 1.f; t22 += 1.f; }
    float2 mm = ((const float2*)(sm + SM_MUML))[jc * 66 + x];   // (mu, ml)
    float2 cc = ((const float2*)(sm + SM_CUCL))[jc * 66 + x];   // (cu, cl)
    float cs2 = sm[SM_CS2 + jc * 66 + x];
    nmu = fmaf(t11, mm.x, fmaf(t12, mm.y, nmu));
    nml = fmaf(t21, mm.x, fmaf(t22, mm.y, nml));
    ncu = fmaf(t11 * t11, cc.x, fmaf(t11 * t12, cs2, fmaf(t12 * t12, cc.y, ncu)));
    ncl = fmaf(t21 * t21, cc.x, fmaf(t21 * t22, cs2, fmaf(t22 * t22, cc.y, ncl)));
    ncs = fmaf(t21 * t11, cc.x,
          fmaf(0.5f * fmaf(t22, t11, t21 * t12), cs2,
          fmaf(t22 * t12, cc.y, ncs)));
}

template<int J0, int JN>
__device__ __forceinline__ void mix_pass(
    uint32_t tmbRow, uint32_t coefA, u64* aX, u64* aY)
{
    #pragma unroll
    for (int jj = 0; jj < JN; jj++) { aX[jj] = 0; aY[jj] = 0; }
    #pragma unroll
    for (int k = 0; k < NB; k++) {
        u64 c2 = LDS64(coefA + (uint32_t)(k * 512));
        #pragma unroll
        for (int jj = 0; jj < JN; jj++) {
            u64 vX, vY;   // (t11,t21), (t12,t22) — warp-uniform broadcast
            asm("ld.shared.v2.u64 {%0,%1},[%2];"
                : "=l"(vX), "=l"(vY)
                : "r"(tmbRow + (uint32_t)(((J0 + jj) * NB + k) * 16)));
            FMA2(aX[jj], c2, vX);
            FMA2(aY[jj], c2, vY);
        }
    }
}

__global__ void __launch_bounds__(NT, 1) acpredict_kernel(
    const float* __restrict__ post_mean, const float* __restrict__ cu_g,
    const float* __restrict__ cl_g, const float* __restrict__ cs_g,
    const float* __restrict__ action, const float* __restrict__ log_noise,
    const float* __restrict__ w_coef, const float* __restrict__ b_coef,
    const float* __restrict__ w_c1, const float* __restrict__ b_c1,
    const float* __restrict__ w_c2, const float* __restrict__ b_c2,
    float* __restrict__ out)
{
    extern __shared__ float sm[];
    const int x   = threadIdx.x;           // 0..63 : batch element
    const int y   = threadIdx.y;           // 0..9  : row group (pair of warps)
    const int tid = y * BX + x;
    const int b0  = blockIdx.x * BX;

    // ---- phase 0: load inputs + prep weights (tmb region holds scratch) ----
    for (int e = tid; e < BX * LSD; e += NT) {
        int bl = e / LSD, d = e % LSD;
        float v = post_mean[(b0 + bl) * LSD + d];
        int j = (d < LOD) ? d : d - LOD;
        sm[SM_MUML + (j * 66 + bl) * 2 + (d < LOD ? 0 : 1)] = v;
    }
    for (int e = tid; e < BX * LOD; e += NT) {
        int bl = e / LOD, j = e % LOD;
        sm[SM_CUCL + (j * 66 + bl) * 2 + 0] = cu_g[(b0 + bl) * LOD + j];
        sm[SM_CUCL + (j * 66 + bl) * 2 + 1] = cl_g[(b0 + bl) * LOD + j];
        sm[SM_CS2 + j * 66 + bl] = 2.f * cs_g[(b0 + bl) * LOD + j];
    }
    for (int e = tid; e < BX * AD; e += NT) {
        int bl = e / AD, d = e % AD;
        sm[PW_ACT + d * 66 + bl] = action[(b0 + bl) * AD + d];
    }
    // w_coef packed as (w[k][j], w[k][j+60]) pairs
    for (int e = tid; e < NB * LSD; e += NT) {
        int k = e / LSD, d = e % LSD;
        int j = (d < LOD) ? d : d - LOD;
        sm[PW_WC + (k * LOD + j) * 2 + (d < LOD ? 0 : 1)] = w_coef[e];
    }
    for (int e = tid; e < HH * AD; e += NT)  sm[PW_W1 + e] = w_c1[e];
    // w_c2 duplicated as (w,w) pairs
    for (int e = tid; e < LSD * HH; e += NT) {
        float v = w_c2[e];
        ((u64*)(sm + PW_W2))[e] = F2U(v, v);
    }
    if (tid < HH)  sm[PW_B1 + tid] = b_c1[tid];
    if (tid < LSD) sm[PW_B2 + tid] = b_c2[tid];
    if (tid < NB)  sm[PW_BC + tid] = b_coef[tid];
    if (tid < LSD) {
        float v = log_noise[tid];
        sm[SM_TC + tid] = (v < 0.f) ? __expf(v) : v + 1.f;
    }
    __syncthreads();

    // ---- phase 1: logits (packed f32x2) + hidden layer ----
    for (int e = tid; e < NB * BX; e += NT) {
        int k = e / BX, bl = e % BX;
        u64 acc = 0;
        const u64* wcP = (const u64*)(sm + PW_WC) + k * LOD;     // warp-uniform
        const u64* mmP = (const u64*)(sm + SM_MUML);
        #pragma unroll 4
        for (int j = 0; j < LOD; j++)
            FMA2(acc, wcP[j], mmP[j * 66 + bl]);
        float2 p = U2F(acc);
        sm[PW_LG + k * 66 + bl] = p.x + p.y + sm[PW_BC + k];
    }
    for (int e = tid; e < HH * BX; e += NT) {
        int i = e / BX, bl = e % BX;
        float hv = sm[PW_B1 + i];
        #pragma unroll
        for (int d = 0; d < AD; d++)
            hv = fmaf(sm[PW_W1 + i * AD + d], sm[PW_ACT + d * 66 + bl], hv);
        sm[PW_H + i * 66 + bl] = fmaxf(hv, 0.f);
    }
    __syncthreads();

    // ---- phase 2: softmax (-> SM_COEF) + control MLP (channel-tiled x3, even waves) ----
    if (tid < BX) {
        const int bl = tid;
        float mx = -1e30f;
        #pragma unroll
        for (int k = 0; k < NB; k++) mx = fmaxf(mx, sm[PW_LG + k * 66 + bl]);
        float ex[NB], sum = 0.f;
        #pragma unroll
        for (int k = 0; k < NB; k++) {
            ex[k] = __expf(sm[PW_LG + k * 66 + bl] - mx);
            sum += ex[k];
        }
        float inv = 1.f / sum;
        #pragma unroll
        for (int k = 0; k < NB; k++) {
            float c = ex[k] * inv;
            ((u64*)(sm + SM_COEF))[k * BX + bl] = F2U(c, c);
        }
    }
    // 40 channel-groups (3 channels) x 32 batch-pairs = 1280 items -> 2 even waves
    for (int e = tid; e < 40 * (BX / 2); e += NT) {
        int g = e / (BX / 2), blp = e % (BX / 2);
        int c0 = g * 3;
        u64 acc[3];
        #pragma unroll
        for (int q = 0; q < 3; q++) {
            float bb = sm[PW_B2 + c0 + q];
            acc[q] = F2U(bb, bb);
        }
        const u64* w2P = (const u64*)(sm + PW_W2);               // warp-uniform dup pairs
        const u64* hP  = (const u64*)(sm + PW_H);                // h[m][2blp..2blp+1]
        #pragma unroll 4
        for (int m = 0; m < HH; m++) {
            u64 hm = hP[m * 33 + blp];
            #pragma unroll
            for (int q = 0; q < 3; q++)
                FMA2(acc[q], w2P[(c0 + q) * HH + m], hm);
        }
        #pragma unroll
        for (int q = 0; q < 3; q++)
            ((u64*)(sm + SM_CTL))[(c0 + q) * 33 + blp] = acc[q];
    }
    __syncthreads();

    // ---- phase 3: wait for pack kernel, load tmb into smem ----
    cudaGridDependencySynchronize();
    {
        float4* t4 = (float4*)sm;
        for (int e = tid; e < LOD * 7 * NB; e += NT) t4[e] = g_tmb[e];
    }
    __syncthreads();

    // ---- phase 4: mix + combine; OUTER LOOP NOT UNROLLED (keep body inside I$) ----
    const uint32_t sbase = (uint32_t)__cvta_generic_to_shared(sm);
    const uint32_t coefA = sbase + SM_COEF * 4 + (uint32_t)x * 8u;

    #pragma unroll 1
    for (int t = 0; t < RPT; t++) {
        const int i = y + BY * t;
        const uint32_t tmbRow = sbase + (uint32_t)(i * 7 * NB * 16);

        float nmu = 0.f, nml = 0.f, ncu = 0.f, ncl = 0.f, ncs = 0.f;
        {   // jj 0..3
            u64 aX[4], aY[4];
            mix_pass<0, 4>(tmbRow, coefA, aX, aY);
            #pragma unroll
            for (int jj = 0; jj < 4; jj++) {
                int jc = max(i + jj - 3, 0);
                combine(aX[jj], aY[jj], jj == 3, jc, x, sm, nmu, nml, ncu, ncl, ncs);
            }
        }
        {   // jj 4..6
            u64 aX[3], aY[3];
            mix_pass<4, 3>(tmbRow, coefA, aX, aY);
            #pragma unroll
            for (int jj = 0; jj < 3; jj++) {
                int jc = min(i + 1 + jj, LOD - 1);
                combine(aX[jj], aY[jj], false, jc, x, sm, nmu, nml, ncu, ncl, ncs);
            }
        }

        // pair barrier: both warps of this y done READING tmb row i
        asm volatile("bar.sync %0, 64;" :: "r"(y + 1) : "memory");

        // stage into this row's own (now dead) tmb slot: 420 floats per row
        float* stg = sm + i * 420;
        stg[0 * 64 + x] = nmu;
        stg[1 * 64 + x] = nml;
        stg[2 * 64 + x] = ncu;
        stg[3 * 64 + x] = ncl;
        stg[4 * 64 + x] = ncs;
    }
    __syncthreads();

    // ---- phase 5: coalesced stores; fold in control + trans_cov ----
    // stage layout: value(q, row i, batch bl) at sm[i*420 + q*64 + bl]
    for (int e = tid; e < BX * 300; e += NT) {
        int bl = e / 300, c = e % 300;
        int q = c / 60, i = c % 60;
        float v = sm[i * 420 + q * 64 + bl];
        int bb = b0 + bl;
        if (c < 120) {
            v += sm[SM_CTL + c * 66 + bl];
            out[bb * 120 + c] = v;
        } else {
            if (c < 240) v += sm[SM_TC + (c - 120)];
            out[NB_B * 60 * q + bb * 60 + i] = v;
        }
    }
}

extern "C" void kernel_launch(void* const* d_in, const int* in_sizes, int n_in,
                              void* d_out, int out_size) {
    const float* post_mean = (const float*)d_in[0];
    const float* cu        = (const float*)d_in[1];
    const float* cl        = (const float*)d_in[2];
    const float* cs        = (const float*)d_in[3];
    const float* action    = (const float*)d_in[4];
    const float* tm11      = (const float*)d_in[5];
    const float* tm12      = (const float*)d_in[6];
    const float* tm21      = (const float*)d_in[7];
    const float* tm22      = (const float*)d_in[8];
    const float* log_noise = (const float*)d_in[9];
    const float* w_coef    = (const float*)d_in[10];
    const float* b_coef    = (const float*)d_in[11];
    const float* w_c1      = (const float*)d_in[12];
    const float* b_c1      = (const float*)d_in[13];
    const float* w_c2      = (const float*)d_in[14];
    const float* b_c2      = (const float*)d_in[15];
    float* out = (float*)d_out;

    static bool attr_done = false;
    if (!attr_done) {
        cudaFuncSetAttribute(acpredict_kernel,
            cudaFuncAttributeMaxDynamicSharedMemorySize, SM_FLOATS * 4);
        attr_done = true;
    }

    // primary: tiny tmb pack
    pack_kernel<<<13, 512>>>(tm11, tm12, tm21, tm22);

    // secondary: fused main kernel with PDL (preamble overlaps pack)
    cudaLaunchConfig_t cfg = {};
    cfg.gridDim = dim3(NB_B / BX);
    cfg.blockDim = dim3(BX, BY);
    cfg.dynamicSmemBytes = SM_FLOATS * 4;
    cfg.stream = 0;
    cudaLaunchAttribute at[1];
    at[0].id = cudaLaunchAttributeProgrammaticStreamSerialization;
    at[0].val.programmaticStreamSerializationAllowed = 1;
    cfg.attrs = at;
    cfg.numAttrs = 1;
    cudaLaunchKernelEx(&cfg, acpredict_kernel,
                       post_mean, cu, cl, cs, action, log_noise,
                       w_coef, b_coef, w_c1, b_c1, w_c2, b_c2, out);
}

// round 16
// speedup vs baseline: 1.2826x; 1.0942x over previous
#include <cuda_runtime.h>
#include <cstdint>

#define NB_B 8192
#define LOD 60
#define LSD 120
#define AD 10
#define NB 15
#define HH 60
#define BX 64
#define BY 10
#define NT 640
#define RPT 6      // rows per thread: 60 = BY * RPT

typedef unsigned long long u64;

// ---- device scratch ----
__device__ float4 g_tmb[LOD * 7 * NB];     // (t11,t21,t12,t22) banded, k fastest

#define FMA2(acc, a, b) asm("fma.rn.f32x2 %0, %1, %2, %0;" : "+l"(acc) : "l"(a), "l"(b))
__device__ __forceinline__ float2 U2F(u64 v){ float2 r; asm("mov.b64 {%0,%1},%2;" : "=f"(r.x), "=f"(r.y) : "l"(v)); return r; }
__device__ __forceinline__ u64 F2U(float x, float y){ u64 r; asm("mov.b64 %0,{%1,%2};" : "=l"(r) : "f"(x), "f"(y)); return r; }
__device__ __forceinline__ u64 LDS64(uint32_t a){ u64 r; asm("ld.shared.b64 %0,[%1];" : "=l"(r) : "r"(a)); return r; }

// ======================= pack kernel (tiny, overlapped via PDL) =======================
__global__ void __launch_bounds__(512) pack_kernel(
    const float* __restrict__ tm11, const float* __restrict__ tm12,
    const float* __restrict__ tm21, const float* __restrict__ tm22)
{
    int idx = blockIdx.x * 512 + threadIdx.x;
    if (idx >= LOD * 7 * NB) return;
    int k = idx % NB;
    int jj = (idx / NB) % 7;
    int i = idx / (NB * 7);
    int j = i + jj - 3;
    float4 v = make_float4(0.f, 0.f, 0.f, 0.f);
    if (j >= 0 && j < LOD) {
        int off = k * LOD * LOD + i * LOD + j;
        v.x = tm11[off]; v.y = tm21[off];
        v.z = tm12[off]; v.w = tm22[off];
    }
    g_tmb[idx] = v;
}

// ======================= fused main kernel =======================
// persistent smem regions (float offsets)
#define SM_TMB   0        // 25200 floats; prep scratch first, then tmb (stage reuses tmb rows)
#define SM_MUML  25200    // float2[60][66] -> 7920
#define SM_CUCL  33120    // 7920
#define SM_CS2   41040    // 3960
#define SM_COEF  45000    // u64[15][64] -> 1920
#define SM_TC    46920    // 120
#define SM_CTL   47040    // float2 pairs -> 7920
#define SM_FLOATS 54960   // 219840 bytes

// prep scratch inside tmb region (dead before tmb load)
#define PW_WC   0         // packed float2[15][60] -> 1800
#define PW_W1   1800      // 600
#define PW_W2   2400      // duplicated float2[120][60] -> 14400
#define PW_B1   16800     // 60
#define PW_B2   16860     // 120
#define PW_BC   16980     // 15 (+pad)
#define PW_ACT  17000     // 10*66 = 660
#define PW_H    17660     // 60*66 = 3960
#define PW_LG   21620     // 15*66 = 990 -> 22610 < 25200

__device__ __forceinline__ void combine(
    u64 aXv, u64 aYv, bool diag, int jc, int x, const float* __restrict__ sm,
    float& nmu, float& nml, float& ncu, float& ncl, float& ncs)
{
    float2 X = U2F(aXv), Y = U2F(aYv);
    float t11 = X.x, t21 = X.y, t12 = Y.x, t22 = Y.y;
    if (diag) { t11 += 1.f; t22 += 1.f; }
    float2 mm = ((const float2*)(sm + SM_MUML))[jc * 66 + x];   // (mu, ml)
    float2 cc = ((const float2*)(sm + SM_CUCL))[jc * 66 + x];   // (cu, cl)
    float cs2 = sm[SM_CS2 + jc * 66 + x];
    nmu = fmaf(t11, mm.x, fmaf(t12, mm.y, nmu));
    nml = fmaf(t21, mm.x, fmaf(t22, mm.y, nml));
    ncu = fmaf(t11 * t11, cc.x, fmaf(t11 * t12, cs2, fmaf(t12 * t12, cc.y, ncu)));
    ncl = fmaf(t21 * t21, cc.x, fmaf(t21 * t22, cs2, fmaf(t22 * t22, cc.y, ncl)));
    ncs = fmaf(t21 * t11, cc.x,
          fmaf(0.5f * fmaf(t22, t11, t21 * t12), cs2,
          fmaf(t22 * t12, cc.y, ncs)));
}

template<int J0, int JN>
__device__ __forceinline__ void mix_pass(
    uint32_t tmbRow, uint32_t coefA, u64* aX, u64* aY)
{
    #pragma unroll
    for (int jj = 0; jj < JN; jj++) { aX[jj] = 0; aY[jj] = 0; }
    #pragma unroll
    for (int k = 0; k < NB; k++) {
        u64 c2 = LDS64(coefA + (uint32_t)(k * 512));
        #pragma unroll
        for (int jj = 0; jj < JN; jj++) {
            u64 vX, vY;   // (t11,t21), (t12,t22) — warp-uniform broadcast
            asm("ld.shared.v2.u64 {%0,%1},[%2];"
                : "=l"(vX), "=l"(vY)
                : "r"(tmbRow + (uint32_t)(((J0 + jj) * NB + k) * 16)));
            FMA2(aX[jj], c2, vX);
            FMA2(aY[jj], c2, vY);
        }
    }
}

__global__ void __launch_bounds__(NT, 1) acpredict_kernel(
    const float* __restrict__ post_mean, const float* __restrict__ cu_g,
    const float* __restrict__ cl_g, const float* __restrict__ cs_g,
    const float* __restrict__ action, const float* __restrict__ log_noise,
    const float* __restrict__ w_coef, const float* __restrict__ b_coef,
    const float* __restrict__ w_c1, const float* __restrict__ b_c1,
    const float* __restrict__ w_c2, const float* __restrict__ b_c2,
    float* __restrict__ out)
{
    extern __shared__ float sm[];
    const int x   = threadIdx.x;           // 0..63 : batch element
    const int y   = threadIdx.y;           // 0..9  : row group (pair of warps)
    const int tid = y * BX + x;
    const int b0  = blockIdx.x * BX;

    // ---- phase 0: load inputs + prep weights (tmb region holds scratch) ----
    for (int e = tid; e < BX * LSD; e += NT) {
        int bl = e / LSD, d = e % LSD;
        float v = post_mean[(b0 + bl) * LSD + d];
        int j = (d < LOD) ? d : d - LOD;
        sm[SM_MUML + (j * 66 + bl) * 2 + (d < LOD ? 0 : 1)] = v;
    }
    for (int e = tid; e < BX * LOD; e += NT) {
        int bl = e / LOD, j = e % LOD;
        sm[SM_CUCL + (j * 66 + bl) * 2 + 0] = cu_g[(b0 + bl) * LOD + j];
        sm[SM_CUCL + (j * 66 + bl) * 2 + 1] = cl_g[(b0 + bl) * LOD + j];
        sm[SM_CS2 + j * 66 + bl] = 2.f * cs_g[(b0 + bl) * LOD + j];
    }
    for (int e = tid; e < BX * AD; e += NT) {
        int bl = e / AD, d = e % AD;
        sm[PW_ACT + d * 66 + bl] = action[(b0 + bl) * AD + d];
    }
    // w_coef packed as (w[k][j], w[k][j+60]) pairs
    for (int e = tid; e < NB * LSD; e += NT) {
        int k = e / LSD, d = e % LSD;
        int j = (d < LOD) ? d : d - LOD;
        sm[PW_WC + (k * LOD + j) * 2 + (d < LOD ? 0 : 1)] = w_coef[e];
    }
    for (int e = tid; e < HH * AD; e += NT)  sm[PW_W1 + e] = w_c1[e];
    // w_c2 duplicated as (w,w) pairs
    for (int e = tid; e < LSD * HH; e += NT) {
        float v = w_c2[e];
        ((u64*)(sm + PW_W2))[e] = F2U(v, v);
    }
    if (tid < HH)  sm[PW_B1 + tid] = b_c1[tid];
    if (tid < LSD) sm[PW_B2 + tid] = b_c2[tid];
    if (tid < NB)  sm[PW_BC + tid] = b_coef[tid];
    if (tid < LSD) {
        float v = log_noise[tid];
        sm[SM_TC + tid] = (v < 0.f) ? __expf(v) : v + 1.f;
    }
    __syncthreads();

    // ---- phase 1: logits (packed f32x2) + hidden layer ----
    for (int e = tid; e < NB * BX; e += NT) {
        int k = e / BX, bl = e % BX;
        u64 acc = 0;
        const u64* wcP = (const u64*)(sm + PW_WC) + k * LOD;     // warp-uniform
        const u64* mmP = (const u64*)(sm + SM_MUML);
        #pragma unroll 4
        for (int j = 0; j < LOD; j++)
            FMA2(acc, wcP[j], mmP[j * 66 + bl]);
        float2 p = U2F(acc);
        sm[PW_LG + k * 66 + bl] = p.x + p.y + sm[PW_BC + k];
    }
    for (int e = tid; e < HH * BX; e += NT) {
        int i = e / BX, bl = e % BX;
        float hv = sm[PW_B1 + i];
        #pragma unroll
        for (int d = 0; d < AD; d++)
            hv = fmaf(sm[PW_W1 + i * AD + d], sm[PW_ACT + d * 66 + bl], hv);
        sm[PW_H + i * 66 + bl] = fmaxf(hv, 0.f);
    }
    __syncthreads();

    // ---- phase 2: softmax (-> SM_COEF) + control MLP (x6 groups, 1 item/thread) ----
    if (tid < BX) {
        const int bl = tid;
        float mx = -1e30f;
        #pragma unroll
        for (int k = 0; k < NB; k++) mx = fmaxf(mx, sm[PW_LG + k * 66 + bl]);
        float ex[NB], sum = 0.f;
        #pragma unroll
        for (int k = 0; k < NB; k++) {
            ex[k] = __expf(sm[PW_LG + k * 66 + bl] - mx);
            sum += ex[k];
        }
        float inv = 1.f / sum;
        #pragma unroll
        for (int k = 0; k < NB; k++) {
            float c = ex[k] * inv;
            ((u64*)(sm + SM_COEF))[k * BX + bl] = F2U(c, c);
        }
    }
    // 20 channel-groups (6 channels) x 32 batch-pairs = 640 items = 1 per thread
    {
        const int g   = tid >> 5;        // 0..19 : channel group (warp-uniform)
        const int blp = tid & 31;        // batch pair 0..31
        const int c0  = g * 6;
        u64 acc[6];
        #pragma unroll
        for (int q = 0; q < 6; q++) {
            float bb = sm[PW_B2 + c0 + q];
            acc[q] = F2U(bb, bb);
        }
        const u64* w2P = (const u64*)(sm + PW_W2);               // warp-uniform dup pairs
        const u64* hP  = (const u64*)(sm + PW_H);                // h[m][2blp..2blp+1]
        #pragma unroll 4
        for (int m = 0; m < HH; m++) {
            u64 hm = hP[m * 33 + blp];
            #pragma unroll
            for (int q = 0; q < 6; q++)
                FMA2(acc[q], w2P[(c0 + q) * HH + m], hm);
        }
        #pragma unroll
        for (int q = 0; q < 6; q++)
            ((u64*)(sm + SM_CTL))[(c0 + q) * 33 + blp] = acc[q];
    }
    __syncthreads();

    // ---- phase 3: wait for pack kernel, load tmb into smem ----
    cudaGridDependencySynchronize();
    {
        float4* t4 = (float4*)sm;
        for (int e = tid; e < LOD * 7 * NB; e += NT) t4[e] = g_tmb[e];
    }
    __syncthreads();

    // ---- phase 4: mix + combine; stage per-row into own dead tmb slot ----
    const uint32_t sbase = (uint32_t)__cvta_generic_to_shared(sm);
    const uint32_t coefA = sbase + SM_COEF * 4 + (uint32_t)x * 8u;

    #pragma unroll
    for (int t = 0; t < RPT; t++) {
        const int i = y + BY * t;
        const uint32_t tmbRow = sbase + (uint32_t)(i * 7 * NB * 16);

        float nmu = 0.f, nml = 0.f, ncu = 0.f, ncl = 0.f, ncs = 0.f;
        {   // jj 0..3
            u64 aX[4], aY[4];
            mix_pass<0, 4>(tmbRow, coefA, aX, aY);
            #pragma unroll
            for (int jj = 0; jj < 4; jj++) {
                int jc = max(i + jj - 3, 0);
                combine(aX[jj], aY[jj], jj == 3, jc, x, sm, nmu, nml, ncu, ncl, ncs);
            }
        }
        {   // jj 4..6
            u64 aX[3], aY[3];
            mix_pass<4, 3>(tmbRow, coefA, aX, aY);
            #pragma unroll
            for (int jj = 0; jj < 3; jj++) {
                int jc = min(i + 1 + jj, LOD - 1);
                combine(aX[jj], aY[jj], false, jc, x, sm, nmu, nml, ncu, ncl, ncs);
            }
        }

        // pair barrier: both warps of this y done READING tmb row i
        asm volatile("bar.sync %0, 64;" :: "r"(y + 1) : "memory");

        // stage into this row's own (now dead) tmb slot: 420 floats per row
        float* stg = sm + i * 420;
        stg[0 * 64 + x] = nmu;
        stg[1 * 64 + x] = nml;
        stg[2 * 64 + x] = ncu;
        stg[3 * 64 + x] = ncl;
        stg[4 * 64 + x] = ncs;
    }
    __syncthreads();

    // ---- phase 5: coalesced stores; incremental (bl, c) indexing ----
    // stage layout: value(q, row i, batch bl) at sm[i*420 + q*64 + bl]
    {
        int bl5 = tid / 300;
        int c5  = tid - bl5 * 300;
        for (int r = 0; r < 30; r++) {
            int q = c5 / 60;
            int i = c5 - q * 60;
            float v = sm[i * 420 + q * 64 + bl5];
            int bb = b0 + bl5;
            if (c5 < 120) {
                v += sm[SM_CTL + c5 * 66 + bl5];
                out[bb * 120 + c5] = v;
            } else {
                if (c5 < 240) v += sm[SM_TC + (c5 - 120)];
                out[NB_B * 60 * q + bb * 60 + i] = v;
            }
            // advance e by NT=640 = 2*300 + 40
            bl5 += 2; c5 += 40;
            if (c5 >= 300) { c5 -= 300; bl5 += 1; }
        }
    }
}

extern "C" void kernel_launch(void* const* d_in, const int* in_sizes, int n_in,
                              void* d_out, int out_size) {
    const float* post_mean = (const float*)d_in[0];
    const float* cu        = (const float*)d_in[1];
    const float* cl        = (const float*)d_in[2];
    const float* cs        = (const float*)d_in[3];
    const float* action    = (const float*)d_in[4];
    const float* tm11      = (const float*)d_in[5];
    const float* tm12      = (const float*)d_in[6];
    const float* tm21      = (const float*)d_in[7];
    const float* tm22      = (const float*)d_in[8];
    const float* log_noise = (const float*)d_in[9];
    const float* w_coef    = (const float*)d_in[10];
    const float* b_coef    = (const float*)d_in[11];
    const float* w_c1      = (const float*)d_in[12];
    const float* b_c1      = (const float*)d_in[13];
    const float* w_c2      = (const float*)d_in[14];
    const float* b_c2      = (const float*)d_in[15];
    float* out = (float*)d_out;

    static bool attr_done = false;
    if (!attr_done) {
        cudaFuncSetAttribute(acpredict_kernel,
            cudaFuncAttributeMaxDynamicSharedMemorySize, SM_FLOATS * 4);
        attr_done = true;
    }

    // primary: tiny tmb pack
    pack_kernel<<<13, 512>>>(tm11, tm12, tm21, tm22);

    // secondary: fused main kernel with PDL (preamble overlaps pack)
    cudaLaunchConfig_t cfg = {};
    cfg.gridDim = dim3(NB_B / BX);
    cfg.blockDim = dim3(BX, BY);
    cfg.dynamicSmemBytes = SM_FLOATS * 4;
    cfg.stream = 0;
    cudaLaunchAttribute at[1];
    at[0].id = cudaLaunchAttributeProgrammaticStreamSerialization;
    at[0].val.programmaticStreamSerializationAllowed = 1;
    cfg.attrs = at;
    cfg.numAttrs = 1;
    cudaLaunchKernelEx(&cfg, acpredict_kernel,
                       post_mean, cu, cl, cs, action, log_noise,
                       w_coef, b_coef, w_c1, b_c1, w_c2, b_c2, out);
}